// round 2
// baseline (speedup 1.0000x reference)
#include <cuda_runtime.h>
#include <math.h>

// Problem constants
#define M_TOK   131072        // B*H*W = 8*128*128
#define C_DIM   128
#define N_SEQ   16384         // H*W per batch
#define NHEADS  4
#define DHEAD   32
#define KS      7

// -------- scratch (static device globals; no allocation in kernel_launch) ----
__device__ float g_xs  [(size_t)M_TOK * C_DIM];       // LN output (reused for LN1 and LN2)
__device__ float g_qkv [(size_t)M_TOK * 3 * C_DIM];   // qkv projections
__device__ float g_attn[(size_t)M_TOK * C_DIM];       // attention output
__device__ float g_x2  [(size_t)M_TOK * C_DIM];       // x after first residual
__device__ float g_h   [(size_t)M_TOK * 4 * C_DIM];   // MLP hidden

// ---------------------------------------------------------------------------
// LayerNorm: one warp per row of 128, float4 per lane.
// ---------------------------------------------------------------------------
__global__ __launch_bounds__(256)
void ln_kernel(const float* __restrict__ x, const float* __restrict__ w,
               const float* __restrict__ b, float* __restrict__ out)
{
    int row  = blockIdx.x * 8 + (threadIdx.x >> 5);
    int lane = threadIdx.x & 31;
    const float4 v = ((const float4*)(x + (size_t)row * C_DIM))[lane];

    float s = v.x + v.y + v.z + v.w;
    #pragma unroll
    for (int o = 16; o; o >>= 1) s += __shfl_xor_sync(0xffffffffu, s, o);
    float mu = s * (1.0f / C_DIM);

    float dx = v.x - mu, dy = v.y - mu, dz = v.z - mu, dw = v.w - mu;
    float sq = dx*dx + dy*dy + dz*dz + dw*dw;
    #pragma unroll
    for (int o = 16; o; o >>= 1) sq += __shfl_xor_sync(0xffffffffu, sq, o);
    float rstd = rsqrtf(sq * (1.0f / C_DIM) + 1e-5f);

    const float4 wv = ((const float4*)w)[lane];
    const float4 bv = ((const float4*)b)[lane];
    float4 o4;
    o4.x = dx * rstd * wv.x + bv.x;
    o4.y = dy * rstd * wv.y + bv.y;
    o4.z = dz * rstd * wv.z + bv.z;
    o4.w = dw * rstd * wv.w + bv.w;
    ((float4*)(out + (size_t)row * C_DIM))[lane] = o4;
}

// ---------------------------------------------------------------------------
// Generic fp32 GEMM: C[M,N] = A[M,K] @ Bw[N,K]^T (+bias, epilogue)
// BM=BN=128, BK=16, 256 threads, 8x8 microtile.
// EPI: 0 = qkv (scale cols<128 by 1/sqrt(32)), 1 = +residual, 2 = exact GELU
// ---------------------------------------------------------------------------
template<int EPI>
__global__ __launch_bounds__(256, 2)
void gemm_kernel(const float* __restrict__ A, const float* __restrict__ Bw,
                 const float* __restrict__ bias, const float* __restrict__ res,
                 float* __restrict__ C, int Nn, int K)
{
    constexpr int BM = 128, BN = 128, BK = 16;
    __shared__ float As[BK][BM + 4];
    __shared__ float Bs[BK][BN + 4];

    const int m0  = blockIdx.y * BM;
    const int n0  = blockIdx.x * BN;
    const int tid = threadIdx.x;
    const int tx  = tid % 16;      // column group
    const int ty  = tid / 16;      // row group

    float acc[8][8];
    #pragma unroll
    for (int i = 0; i < 8; i++)
        #pragma unroll
        for (int j = 0; j < 8; j++) acc[i][j] = 0.0f;

    const int lrow = tid >> 1;          // 0..127
    const int lk   = (tid & 1) * 8;     // 0 or 8
    const float* Aptr = A  + (size_t)(m0 + lrow) * K + lk;
    const float* Bptr = Bw + (size_t)(n0 + lrow) * K + lk;

    for (int k0 = 0; k0 < K; k0 += BK) {
        float4 av0 = *(const float4*)(Aptr + k0);
        float4 av1 = *(const float4*)(Aptr + k0 + 4);
        float4 bv0 = *(const float4*)(Bptr + k0);
        float4 bv1 = *(const float4*)(Bptr + k0 + 4);
        __syncthreads();
        As[lk+0][lrow] = av0.x; As[lk+1][lrow] = av0.y;
        As[lk+2][lrow] = av0.z; As[lk+3][lrow] = av0.w;
        As[lk+4][lrow] = av1.x; As[lk+5][lrow] = av1.y;
        As[lk+6][lrow] = av1.z; As[lk+7][lrow] = av1.w;
        Bs[lk+0][lrow] = bv0.x; Bs[lk+1][lrow] = bv0.y;
        Bs[lk+2][lrow] = bv0.z; Bs[lk+3][lrow] = bv0.w;
        Bs[lk+4][lrow] = bv1.x; Bs[lk+5][lrow] = bv1.y;
        Bs[lk+6][lrow] = bv1.z; Bs[lk+7][lrow] = bv1.w;
        __syncthreads();

        #pragma unroll
        for (int kk = 0; kk < BK; kk++) {
            float4 a0 = *(const float4*)&As[kk][ty * 8];
            float4 a1 = *(const float4*)&As[kk][ty * 8 + 4];
            float4 b0 = *(const float4*)&Bs[kk][tx * 8];
            float4 b1 = *(const float4*)&Bs[kk][tx * 8 + 4];
            float ar[8] = {a0.x, a0.y, a0.z, a0.w, a1.x, a1.y, a1.z, a1.w};
            float br[8] = {b0.x, b0.y, b0.z, b0.w, b1.x, b1.y, b1.z, b1.w};
            #pragma unroll
            for (int i = 0; i < 8; i++)
                #pragma unroll
                for (int j = 0; j < 8; j++)
                    acc[i][j] = fmaf(ar[i], br[j], acc[i][j]);
        }
    }

    // Epilogue
    #pragma unroll
    for (int i = 0; i < 8; i++) {
        int row = m0 + ty * 8 + i;
        #pragma unroll
        for (int jj = 0; jj < 8; jj += 4) {
            int col = n0 + tx * 8 + jj;
            float4 bb = *(const float4*)&bias[col];
            float4 v;
            v.x = acc[i][jj+0] + bb.x;
            v.y = acc[i][jj+1] + bb.y;
            v.z = acc[i][jj+2] + bb.z;
            v.w = acc[i][jj+3] + bb.w;
            if (EPI == 0) {
                if (col < 128) {   // q region: scale by d^-0.5
                    const float s = 0.17677669529663687f;
                    v.x *= s; v.y *= s; v.z *= s; v.w *= s;
                }
            } else if (EPI == 1) {
                float4 r = *(const float4*)&res[(size_t)row * Nn + col];
                v.x += r.x; v.y += r.y; v.z += r.z; v.w += r.w;
            } else if (EPI == 2) {
                const float c = 0.70710678118654752f;
                v.x = 0.5f * v.x * (1.0f + erff(v.x * c));
                v.y = 0.5f * v.y * (1.0f + erff(v.y * c));
                v.z = 0.5f * v.z * (1.0f + erff(v.z * c));
                v.w = 0.5f * v.w * (1.0f + erff(v.w * c));
            }
            *(float4*)&C[(size_t)row * Nn + col] = v;
        }
    }
}

// ---------------------------------------------------------------------------
// Sliding-window attention: one warp per (token, head); lane = d index.
// ---------------------------------------------------------------------------
__global__ __launch_bounds__(256)
void attn_kernel(const float* __restrict__ qkv, const float* __restrict__ rpb,
                 float* __restrict__ out)
{
    int gw   = blockIdx.x * 8 + (threadIdx.x >> 5);   // global warp id over M_TOK*NHEADS
    int lane = threadIdx.x & 31;
    int h = gw & (NHEADS - 1);
    int t = gw >> 2;                 // global token index (b*N + n)
    int n = t & (N_SEQ - 1);         // position within sequence
    int bbase = t - n;               // b*N

    int s = n - KS / 2;
    if (s < 0) s = 0;
    if (s > N_SEQ - KS) s = N_SEQ - KS;

    float q = qkv[(size_t)t * 384 + h * DHEAD + lane];   // already scaled by d^-0.5

    float logits[KS];
    #pragma unroll
    for (int j = 0; j < KS; j++) {
        const float* krow = qkv + (size_t)(bbase + s + j) * 384 + 128 + h * DHEAD;
        float p = q * krow[lane];
        #pragma unroll
        for (int o = 16; o; o >>= 1) p += __shfl_xor_sync(0xffffffffu, p, o);
        logits[j] = p + rpb[h * (2 * KS - 1) + (s + j - n + KS - 1)];
    }

    float mx = logits[0];
    #pragma unroll
    for (int j = 1; j < KS; j++) mx = fmaxf(mx, logits[j]);

    float pj[KS], den = 0.0f;
    #pragma unroll
    for (int j = 0; j < KS; j++) { pj[j] = __expf(logits[j] - mx); den += pj[j]; }
    float inv = 1.0f / den;

    float o = 0.0f;
    #pragma unroll
    for (int j = 0; j < KS; j++) {
        const float* vrow = qkv + (size_t)(bbase + s + j) * 384 + 256 + h * DHEAD;
        o += pj[j] * vrow[lane];
    }
    out[(size_t)t * C_DIM + h * DHEAD + lane] = o * inv;
}

// ---------------------------------------------------------------------------
extern "C" void kernel_launch(void* const* d_in, const int* in_sizes, int n_in,
                              void* d_out, int out_size)
{
    const float* x      = (const float*)d_in[0];
    const float* n1w    = (const float*)d_in[1];
    const float* n1b    = (const float*)d_in[2];
    const float* qkvw   = (const float*)d_in[3];
    const float* qkvb   = (const float*)d_in[4];
    const float* rpb    = (const float*)d_in[5];
    const float* projw  = (const float*)d_in[6];
    const float* projb  = (const float*)d_in[7];
    const float* n2w    = (const float*)d_in[8];
    const float* n2b    = (const float*)d_in[9];
    const float* fc1w   = (const float*)d_in[10];
    const float* fc1b   = (const float*)d_in[11];
    const float* fc2w   = (const float*)d_in[12];
    const float* fc2b   = (const float*)d_in[13];
    float* out = (float*)d_out;

    float *xs, *qkv, *attn, *x2, *hb;
    cudaGetSymbolAddress((void**)&xs,   g_xs);
    cudaGetSymbolAddress((void**)&qkv,  g_qkv);
    cudaGetSymbolAddress((void**)&attn, g_attn);
    cudaGetSymbolAddress((void**)&x2,   g_x2);
    cudaGetSymbolAddress((void**)&hb,   g_h);

    // 1. LN1
    ln_kernel<<<M_TOK / 8, 256>>>(x, n1w, n1b, xs);
    // 2. QKV projection (+bias, q scaled)
    gemm_kernel<0><<<dim3(384 / 128, M_TOK / 128), 256>>>(xs, qkvw, qkvb, nullptr, qkv, 384, 128);
    // 3. Sliding-window attention
    attn_kernel<<<(M_TOK * NHEADS) / 8, 256>>>(qkv, rpb, attn);
    // 4. Output projection + residual (original x)
    gemm_kernel<1><<<dim3(128 / 128, M_TOK / 128), 256>>>(attn, projw, projb, x, x2, 128, 128);
    // 5. LN2
    ln_kernel<<<M_TOK / 8, 256>>>(x2, n2w, n2b, xs);
    // 6. FC1 + exact GELU
    gemm_kernel<2><<<dim3(512 / 128, M_TOK / 128), 256>>>(xs, fc1w, fc1b, nullptr, hb, 512, 128);
    // 7. FC2 + residual (x2) -> out
    gemm_kernel<1><<<dim3(128 / 128, M_TOK / 128), 256>>>(hb, fc2w, fc2b, x2, out, 128, 512);
}

// round 4
// speedup vs baseline: 3.0148x; 3.0148x over previous
#include <cuda_runtime.h>
#include <cuda_bf16.h>
#include <math.h>
#include <stdint.h>

// Problem constants
#define M_TOK   131072        // B*H*W
#define C_DIM   128
#define N_SEQ   16384
#define NHEADS  4
#define DHEAD   32
#define KS      7

// -------- scratch buffers (static device globals) ---------------------------
__device__ __nv_bfloat16 g_xsb  [(size_t)M_TOK * C_DIM];   // LN output (bf16 GEMM A)
__device__ float         g_qkv  [(size_t)M_TOK * 384];     // qkv (fp32 for attention)
__device__ __nv_bfloat16 g_attnb[(size_t)M_TOK * C_DIM];   // attention out (bf16)
__device__ float         g_x2   [(size_t)M_TOK * C_DIM];   // residual trunk after proj
__device__ __nv_bfloat16 g_hb   [(size_t)M_TOK * 512];     // MLP hidden (bf16)
__device__ __nv_bfloat16 g_wqkv [384 * 128];
__device__ __nv_bfloat16 g_wproj[128 * 128];
__device__ __nv_bfloat16 g_w1   [512 * 128];
__device__ __nv_bfloat16 g_w2   [128 * 512];

// ---------------------------------------------------------------------------
// PTX helpers (all plain compute_103-legal: cp.async / ldmatrix / mma.sync)
// ---------------------------------------------------------------------------
__device__ __forceinline__ uint32_t smem_u32(const void* p) {
    uint32_t a;
    asm("{ .reg .u64 t; cvta.to.shared.u64 t, %1; cvt.u32.u64 %0, t; }" : "=r"(a) : "l"(p));
    return a;
}
__device__ __forceinline__ void cp_async16(uint32_t dst, const void* src) {
    asm volatile("cp.async.cg.shared.global [%0], [%1], 16;" :: "r"(dst), "l"(src));
}
__device__ __forceinline__ void ldsm4(uint32_t* r, uint32_t addr) {
    asm volatile("ldmatrix.sync.aligned.m8n8.x4.shared.b16 {%0,%1,%2,%3}, [%4];"
                 : "=r"(r[0]), "=r"(r[1]), "=r"(r[2]), "=r"(r[3]) : "r"(addr));
}
__device__ __forceinline__ void mma_bf16(float* c, const uint32_t* a, uint32_t b0, uint32_t b1) {
    asm volatile(
        "mma.sync.aligned.m16n8k16.row.col.f32.bf16.bf16.f32 "
        "{%0,%1,%2,%3}, {%4,%5,%6,%7}, {%8,%9}, {%0,%1,%2,%3};"
        : "+f"(c[0]), "+f"(c[1]), "+f"(c[2]), "+f"(c[3])
        : "r"(a[0]), "r"(a[1]), "r"(a[2]), "r"(a[3]), "r"(b0), "r"(b1));
}

// ---------------------------------------------------------------------------
// LayerNorm: one warp per row, bf16 output.
// ---------------------------------------------------------------------------
__global__ __launch_bounds__(256)
void ln_kernel(const float* __restrict__ x, const float* __restrict__ w,
               const float* __restrict__ b, __nv_bfloat16* __restrict__ out)
{
    int row  = blockIdx.x * 8 + (threadIdx.x >> 5);
    int lane = threadIdx.x & 31;
    const float4 v = ((const float4*)(x + (size_t)row * C_DIM))[lane];

    float s = v.x + v.y + v.z + v.w;
    #pragma unroll
    for (int o = 16; o; o >>= 1) s += __shfl_xor_sync(0xffffffffu, s, o);
    float mu = s * (1.0f / C_DIM);

    float dx = v.x - mu, dy = v.y - mu, dz = v.z - mu, dw = v.w - mu;
    float sq = dx*dx + dy*dy + dz*dz + dw*dw;
    #pragma unroll
    for (int o = 16; o; o >>= 1) sq += __shfl_xor_sync(0xffffffffu, sq, o);
    float rstd = rsqrtf(sq * (1.0f / C_DIM) + 1e-5f);

    const float4 wv = ((const float4*)w)[lane];
    const float4 bv = ((const float4*)b)[lane];
    float o0 = dx * rstd * wv.x + bv.x;
    float o1 = dy * rstd * wv.y + bv.y;
    float o2 = dz * rstd * wv.z + bv.z;
    float o3 = dw * rstd * wv.w + bv.w;
    __nv_bfloat162* op = (__nv_bfloat162*)(out + (size_t)row * C_DIM + lane * 4);
    op[0] = __floats2bfloat162_rn(o0, o1);
    op[1] = __floats2bfloat162_rn(o2, o3);
}

// ---------------------------------------------------------------------------
// fp32 -> bf16 weight conversion
// ---------------------------------------------------------------------------
__global__ void cvt_kernel(const float* __restrict__ src, __nv_bfloat16* __restrict__ dst, int n)
{
    int i = blockIdx.x * 256 + threadIdx.x;
    if (i < n) dst[i] = __float2bfloat16_rn(src[i]);
}

// ---------------------------------------------------------------------------
// HMMA bf16 GEMM: C[M,N] = A[M,K] @ Bw[N,K]^T, 128x128 tile per CTA.
// 8 warps (4 in M x 2 in N), warp tile 32x64, BK=64 double-buffered cp.async,
// SW128 swizzle, ldmatrix.x4 operand fetch, fp32 accumulators.
// EPI: 0 = +bias (fp32 out)   1 = +bias+res (fp32 out)   2 = +bias, GELU (bf16 out)
// ---------------------------------------------------------------------------
template<int KDIM>
__device__ __forceinline__ void load_chunk(uint32_t sbuf,
    const __nv_bfloat16* __restrict__ A, const __nv_bfloat16* __restrict__ Bw,
    int m0, int n0, int c, int tid)
{
    const int r  = tid >> 1;            // 0..127 : tile row
    const int s0 = (tid & 1) * 4;       // first 16B segment (of 8 per 128B row)
    const __nv_bfloat16* Ap = A  + (size_t)(m0 + r) * KDIM + c * 64 + s0 * 8;
    const __nv_bfloat16* Bp = Bw + (size_t)(n0 + r) * KDIM + c * 64 + s0 * 8;
    uint32_t bo0 = (uint32_t)(r * 128 + s0 * 16);
    #pragma unroll
    for (int p = 0; p < 4; p++) {
        uint32_t bo = bo0 + p * 16;
        uint32_t sw = bo ^ ((bo >> 3) & 0x70);
        cp_async16(sbuf + sw,          Ap + p * 8);
        cp_async16(sbuf + 16384u + sw, Bp + p * 8);
    }
    asm volatile("cp.async.commit_group;" ::: "memory");
}

template<int EPI, int KDIM>
__global__ __launch_bounds__(256, 2)
void gemm_tc(const __nv_bfloat16* __restrict__ A, const __nv_bfloat16* __restrict__ Bw,
             const float* __restrict__ bias, const float* __restrict__ res,
             void* __restrict__ Cout, int ldc)
{
    constexpr int NCH = KDIM / 64;
    extern __shared__ char dsm[];
    const uint32_t sbase = (smem_u32(dsm) + 127u) & ~127u;

    const int tid  = threadIdx.x;
    const int lane = tid & 31;
    const int w    = tid >> 5;
    const int wm   = w & 3;            // 0..3 -> 32-row band
    const int wn   = w >> 2;           // 0..1 -> 64-col band
    const int m0 = blockIdx.y * 128, n0 = blockIdx.x * 128;

    float acc[2][8][4];
    #pragma unroll
    for (int i = 0; i < 2; i++)
        #pragma unroll
        for (int j = 0; j < 8; j++)
            #pragma unroll
            for (int q = 0; q < 4; q++) acc[i][j][q] = 0.0f;

    // ldmatrix lane address components (within-chunk byte offsets, pre-swizzle)
    // A: matrices {m-lo,k-lo},{m-hi,k-lo},{m-lo,k-hi},{m-hi,k-hi}
    const int a_row = wm * 32 + ((lane >> 3) & 1) * 8 + (lane & 7);   // + mi*16
    const int a_kof = (lane >> 4) * 8;                                // + ks*16
    // B: matrices {n-lo,k-lo},{n-lo,k-hi},{n-hi,k-lo},{n-hi,k-hi}
    const int b_row = wn * 64 + (lane >> 4) * 8 + (lane & 7);         // + nj*16
    const int b_kof = ((lane >> 3) & 1) * 8;                          // + ks*16

    load_chunk<KDIM>(sbase, A, Bw, m0, n0, 0, tid);

    #pragma unroll 1
    for (int c = 0; c < NCH; c++) {
        if (c + 1 < NCH) {
            load_chunk<KDIM>(sbase + (uint32_t)((c + 1) & 1) * 32768u, A, Bw, m0, n0, c + 1, tid);
            asm volatile("cp.async.wait_group 1;" ::: "memory");
        } else {
            asm volatile("cp.async.wait_group 0;" ::: "memory");
        }
        __syncthreads();

        const uint32_t Ab = sbase + (uint32_t)(c & 1) * 32768u;
        const uint32_t Bb = Ab + 16384u;

        #pragma unroll
        for (int ks = 0; ks < 4; ks++) {
            uint32_t a[2][4];
            #pragma unroll
            for (int mi = 0; mi < 2; mi++) {
                uint32_t bo = (uint32_t)((a_row + mi * 16) * 128 + (a_kof + ks * 16) * 2);
                ldsm4(a[mi], Ab + (bo ^ ((bo >> 3) & 0x70)));
            }
            #pragma unroll
            for (int nj = 0; nj < 4; nj++) {
                uint32_t b[4];
                uint32_t bo = (uint32_t)((b_row + nj * 16) * 128 + (b_kof + ks * 16) * 2);
                ldsm4(b, Bb + (bo ^ ((bo >> 3) & 0x70)));
                mma_bf16(acc[0][2*nj],   a[0], b[0], b[1]);
                mma_bf16(acc[0][2*nj+1], a[0], b[2], b[3]);
                mma_bf16(acc[1][2*nj],   a[1], b[0], b[1]);
                mma_bf16(acc[1][2*nj+1], a[1], b[2], b[3]);
            }
        }
        __syncthreads();
    }

    // ---- epilogue ----
    const int er = lane >> 2;            // row within 16-row tile (0..7)
    const int ec = (lane & 3) * 2;       // col pair within 8-col tile
    #pragma unroll
    for (int mi = 0; mi < 2; mi++) {
        #pragma unroll
        for (int ns = 0; ns < 8; ns++) {
            int row = m0 + wm * 32 + mi * 16 + er;
            int col = n0 + wn * 64 + ns * 8 + ec;
            float2 bb = *(const float2*)&bias[col];
            float v0 = acc[mi][ns][0] + bb.x;
            float v1 = acc[mi][ns][1] + bb.y;
            float v2 = acc[mi][ns][2] + bb.x;
            float v3 = acc[mi][ns][3] + bb.y;
            if (EPI == 1) {
                float2 r0 = *(const float2*)&res[(size_t)row * ldc + col];
                float2 r1 = *(const float2*)&res[(size_t)(row + 8) * ldc + col];
                v0 += r0.x; v1 += r0.y; v2 += r1.x; v3 += r1.y;
            }
            if (EPI == 2) {
                const float cst = 0.70710678118654752f;
                v0 = 0.5f * v0 * (1.0f + erff(v0 * cst));
                v1 = 0.5f * v1 * (1.0f + erff(v1 * cst));
                v2 = 0.5f * v2 * (1.0f + erff(v2 * cst));
                v3 = 0.5f * v3 * (1.0f + erff(v3 * cst));
                __nv_bfloat16* Cb = (__nv_bfloat16*)Cout;
                *(__nv_bfloat162*)&Cb[(size_t)row * ldc + col]       = __floats2bfloat162_rn(v0, v1);
                *(__nv_bfloat162*)&Cb[(size_t)(row + 8) * ldc + col] = __floats2bfloat162_rn(v2, v3);
            } else {
                float* Cf = (float*)Cout;
                *(float2*)&Cf[(size_t)row * ldc + col]       = make_float2(v0, v1);
                *(float2*)&Cf[(size_t)(row + 8) * ldc + col] = make_float2(v2, v3);
            }
        }
    }
}

// ---------------------------------------------------------------------------
// Sliding-window attention: warp per (token, head); fp32 qkv in, bf16 out.
// q scaled here by d^-0.5.
// ---------------------------------------------------------------------------
__global__ __launch_bounds__(256)
void attn_kernel(const float* __restrict__ qkv, const float* __restrict__ rpb,
                 __nv_bfloat16* __restrict__ out)
{
    int gw   = blockIdx.x * 8 + (threadIdx.x >> 5);
    int lane = threadIdx.x & 31;
    int h = gw & (NHEADS - 1);
    int t = gw >> 2;
    int n = t & (N_SEQ - 1);
    int bbase = t - n;

    int s = n - KS / 2;
    if (s < 0) s = 0;
    if (s > N_SEQ - KS) s = N_SEQ - KS;

    float q = qkv[(size_t)t * 384 + h * DHEAD + lane] * 0.17677669529663687f;

    float logits[KS];
    #pragma unroll
    for (int j = 0; j < KS; j++) {
        const float* krow = qkv + (size_t)(bbase + s + j) * 384 + 128 + h * DHEAD;
        float p = q * krow[lane];
        #pragma unroll
        for (int o = 16; o; o >>= 1) p += __shfl_xor_sync(0xffffffffu, p, o);
        logits[j] = p + rpb[h * (2 * KS - 1) + (s + j - n + KS - 1)];
    }

    float mx = logits[0];
    #pragma unroll
    for (int j = 1; j < KS; j++) mx = fmaxf(mx, logits[j]);

    float pj[KS], den = 0.0f;
    #pragma unroll
    for (int j = 0; j < KS; j++) { pj[j] = __expf(logits[j] - mx); den += pj[j]; }
    float inv = 1.0f / den;

    float o = 0.0f;
    #pragma unroll
    for (int j = 0; j < KS; j++) {
        const float* vrow = qkv + (size_t)(bbase + s + j) * 384 + 256 + h * DHEAD;
        o += pj[j] * vrow[lane];
    }
    out[(size_t)t * C_DIM + h * DHEAD + lane] = __float2bfloat16_rn(o * inv);
}

// ---------------------------------------------------------------------------
extern "C" void kernel_launch(void* const* d_in, const int* in_sizes, int n_in,
                              void* d_out, int out_size)
{
    const float* x      = (const float*)d_in[0];
    const float* n1w    = (const float*)d_in[1];
    const float* n1b    = (const float*)d_in[2];
    const float* qkvw   = (const float*)d_in[3];
    const float* qkvb   = (const float*)d_in[4];
    const float* rpb    = (const float*)d_in[5];
    const float* projw  = (const float*)d_in[6];
    const float* projb  = (const float*)d_in[7];
    const float* n2w    = (const float*)d_in[8];
    const float* n2b    = (const float*)d_in[9];
    const float* fc1w   = (const float*)d_in[10];
    const float* fc1b   = (const float*)d_in[11];
    const float* fc2w   = (const float*)d_in[12];
    const float* fc2b   = (const float*)d_in[13];
    float* out = (float*)d_out;

    __nv_bfloat16 *xsb, *attnb, *hb, *wqkv, *wproj, *w1, *w2;
    float *qkv, *x2;
    cudaGetSymbolAddress((void**)&xsb,   g_xsb);
    cudaGetSymbolAddress((void**)&qkv,   g_qkv);
    cudaGetSymbolAddress((void**)&attnb, g_attnb);
    cudaGetSymbolAddress((void**)&x2,    g_x2);
    cudaGetSymbolAddress((void**)&hb,    g_hb);
    cudaGetSymbolAddress((void**)&wqkv,  g_wqkv);
    cudaGetSymbolAddress((void**)&wproj, g_wproj);
    cudaGetSymbolAddress((void**)&w1,    g_w1);
    cudaGetSymbolAddress((void**)&w2,    g_w2);

    const int SMEM = 65536 + 128;
    cudaFuncSetAttribute(gemm_tc<0,128>, cudaFuncAttributeMaxDynamicSharedMemorySize, SMEM);
    cudaFuncSetAttribute(gemm_tc<1,128>, cudaFuncAttributeMaxDynamicSharedMemorySize, SMEM);
    cudaFuncSetAttribute(gemm_tc<2,128>, cudaFuncAttributeMaxDynamicSharedMemorySize, SMEM);
    cudaFuncSetAttribute(gemm_tc<1,512>, cudaFuncAttributeMaxDynamicSharedMemorySize, SMEM);

    // weight conversion (cheap, once per launch)
    cvt_kernel<<<(384*128 + 255)/256, 256>>>(qkvw,  wqkv,  384*128);
    cvt_kernel<<<(128*128 + 255)/256, 256>>>(projw, wproj, 128*128);
    cvt_kernel<<<(512*128 + 255)/256, 256>>>(fc1w,  w1,    512*128);
    cvt_kernel<<<(128*512 + 255)/256, 256>>>(fc2w,  w2,    128*512);

    // 1. LN1 -> bf16
    ln_kernel<<<M_TOK / 8, 256>>>(x, n1w, n1b, xsb);
    // 2. QKV projection (+bias) -> fp32
    gemm_tc<0,128><<<dim3(3, M_TOK/128), 256, SMEM>>>(xsb, wqkv, qkvb, nullptr, qkv, 384);
    // 3. attention -> bf16
    attn_kernel<<<(M_TOK * NHEADS) / 8, 256>>>(qkv, rpb, attnb);
    // 4. proj + residual(x) -> fp32 x2
    gemm_tc<1,128><<<dim3(1, M_TOK/128), 256, SMEM>>>(attnb, wproj, projb, x, x2, 128);
    // 5. LN2 -> bf16
    ln_kernel<<<M_TOK / 8, 256>>>(x2, n2w, n2b, xsb);
    // 6. FC1 + GELU -> bf16
    gemm_tc<2,128><<<dim3(4, M_TOK/128), 256, SMEM>>>(xsb, w1, fc1b, nullptr, hb, 512);
    // 7. FC2 + residual(x2) -> out fp32
    gemm_tc<1,512><<<dim3(1, M_TOK/128), 256, SMEM>>>(hb, w2, fc2b, x2, out, 128);
}

// round 5
// speedup vs baseline: 3.1079x; 1.0309x over previous
#include <cuda_runtime.h>
#include <cuda_bf16.h>
#include <math.h>
#include <stdint.h>

// Problem constants
#define M_TOK   131072        // B*H*W
#define C_DIM   128
#define N_SEQ   16384
#define NHEADS  4
#define DHEAD   32
#define KS      7

typedef __nv_bfloat16 bf16;

// -------- scratch buffers (static device globals) ---------------------------
__device__ bf16  g_xsb  [(size_t)M_TOK * 128];   // LN output (bf16 GEMM A)
__device__ bf16  g_qkvb [(size_t)M_TOK * 384];   // qkv (bf16)
__device__ bf16  g_attnb[(size_t)M_TOK * 128];   // attention out (bf16)
__device__ float g_x2   [(size_t)M_TOK * 128];   // residual trunk after proj
__device__ bf16  g_wqkv [384 * 128];
__device__ bf16  g_wproj[128 * 128];
__device__ bf16  g_w1   [512 * 128];
__device__ bf16  g_w2   [128 * 512];

// ---------------------------------------------------------------------------
// PTX helpers (plain compute_103-legal)
// ---------------------------------------------------------------------------
__device__ __forceinline__ uint32_t smem_u32(const void* p) {
    uint32_t a;
    asm("{ .reg .u64 t; cvta.to.shared.u64 t, %1; cvt.u32.u64 %0, t; }" : "=r"(a) : "l"(p));
    return a;
}
__device__ __forceinline__ void cp_async16(uint32_t dst, const void* src) {
    asm volatile("cp.async.cg.shared.global [%0], [%1], 16;" :: "r"(dst), "l"(src));
}
__device__ __forceinline__ void ldsm4(uint32_t* r, uint32_t addr) {
    asm volatile("ldmatrix.sync.aligned.m8n8.x4.shared.b16 {%0,%1,%2,%3}, [%4];"
                 : "=r"(r[0]), "=r"(r[1]), "=r"(r[2]), "=r"(r[3]) : "r"(addr));
}
__device__ __forceinline__ void mma_bf16(float* c, const uint32_t* a, uint32_t b0, uint32_t b1) {
    asm volatile(
        "mma.sync.aligned.m16n8k16.row.col.f32.bf16.bf16.f32 "
        "{%0,%1,%2,%3}, {%4,%5,%6,%7}, {%8,%9}, {%0,%1,%2,%3};"
        : "+f"(c[0]), "+f"(c[1]), "+f"(c[2]), "+f"(c[3])
        : "r"(a[0]), "r"(a[1]), "r"(a[2]), "r"(a[3]), "r"(b0), "r"(b1));
}

// One 64-wide K-chunk of HMMA on resident swizzled tiles (128B rows, 64 bf16).
__device__ __forceinline__ void mma_chunk(uint32_t Ab, uint32_t Bb,
                                          float (&acc)[2][8][4],
                                          int a_row, int a_kof, int b_row, int b_kof)
{
    #pragma unroll
    for (int ks = 0; ks < 4; ks++) {
        uint32_t a[2][4];
        #pragma unroll
        for (int mi = 0; mi < 2; mi++) {
            uint32_t bo = (uint32_t)((a_row + mi * 16) * 128 + (a_kof + ks * 16) * 2);
            ldsm4(a[mi], Ab + (bo ^ ((bo >> 3) & 0x70)));
        }
        #pragma unroll
        for (int nj = 0; nj < 4; nj++) {
            uint32_t b[4];
            uint32_t bo = (uint32_t)((b_row + nj * 16) * 128 + (b_kof + ks * 16) * 2);
            ldsm4(b, Bb + (bo ^ ((bo >> 3) & 0x70)));
            mma_bf16(acc[0][2*nj],   a[0], b[0], b[1]);
            mma_bf16(acc[0][2*nj+1], a[0], b[2], b[3]);
            mma_bf16(acc[1][2*nj],   a[1], b[0], b[1]);
            mma_bf16(acc[1][2*nj+1], a[1], b[2], b[3]);
        }
    }
}

// Streaming loader: one 64-K chunk of A & B tiles from global (row stride KDIM).
template<int KDIM>
__device__ __forceinline__ void load_chunk(uint32_t sbuf,
    const bf16* __restrict__ A, const bf16* __restrict__ Bw,
    int m0, int n0, int c, int tid)
{
    const int r  = tid >> 1;
    const int s0 = (tid & 1) * 4;
    const bf16* Ap = A  + (size_t)(m0 + r) * KDIM + c * 64 + s0 * 8;
    const bf16* Bp = Bw + (size_t)(n0 + r) * KDIM + c * 64 + s0 * 8;
    uint32_t bo0 = (uint32_t)(r * 128 + s0 * 16);
    #pragma unroll
    for (int p = 0; p < 4; p++) {
        uint32_t bo = bo0 + p * 16;
        uint32_t sw = bo ^ ((bo >> 3) & 0x70);
        cp_async16(sbuf + sw,          Ap + p * 8);
        cp_async16(sbuf + 16384u + sw, Bp + p * 8);
    }
    asm volatile("cp.async.commit_group;" ::: "memory");
}

// Resident loader: full 128x128 bf16 tile -> 2-chunk swizzled layout.
__device__ __forceinline__ void load_tile(uint32_t dst, const bf16* __restrict__ src,
                                          int rstride, int tid)
{
    const int r  = tid >> 1;
    const int s0 = (tid & 1) * 4;
    const bf16* p = src + (size_t)r * rstride;
    #pragma unroll
    for (int c = 0; c < 2; c++) {
        #pragma unroll
        for (int q = 0; q < 4; q++) {
            uint32_t bo = (uint32_t)(r * 128 + (s0 + q) * 16);
            uint32_t sw = bo ^ ((bo >> 3) & 0x70);
            cp_async16(dst + c * 16384u + sw, p + c * 64 + (s0 + q) * 8);
        }
    }
}

// ---------------------------------------------------------------------------
// LayerNorm (LN1): one warp per row, bf16 output.
// ---------------------------------------------------------------------------
__global__ __launch_bounds__(256)
void ln_kernel(const float* __restrict__ x, const float* __restrict__ w,
               const float* __restrict__ b, bf16* __restrict__ out)
{
    int row  = blockIdx.x * 8 + (threadIdx.x >> 5);
    int lane = threadIdx.x & 31;
    const float4 v = ((const float4*)(x + (size_t)row * 128))[lane];

    float s = v.x + v.y + v.z + v.w;
    #pragma unroll
    for (int o = 16; o; o >>= 1) s += __shfl_xor_sync(0xffffffffu, s, o);
    float mu = s * (1.0f / 128.0f);

    float dx = v.x - mu, dy = v.y - mu, dz = v.z - mu, dw = v.w - mu;
    float sq = dx*dx + dy*dy + dz*dz + dw*dw;
    #pragma unroll
    for (int o = 16; o; o >>= 1) sq += __shfl_xor_sync(0xffffffffu, sq, o);
    float rstd = rsqrtf(sq * (1.0f / 128.0f) + 1e-5f);

    const float4 wv = ((const float4*)w)[lane];
    const float4 bv = ((const float4*)b)[lane];
    __nv_bfloat162* op = (__nv_bfloat162*)(out + (size_t)row * 128 + lane * 4);
    op[0] = __floats2bfloat162_rn(dx * rstd * wv.x + bv.x, dy * rstd * wv.y + bv.y);
    op[1] = __floats2bfloat162_rn(dz * rstd * wv.z + bv.z, dw * rstd * wv.w + bv.w);
}

// ---------------------------------------------------------------------------
// Fused weight conversion (all 4 matrices, one launch)
// ---------------------------------------------------------------------------
__global__ void cvt_all(const float* __restrict__ qkvw, const float* __restrict__ projw,
                        const float* __restrict__ fc1w, const float* __restrict__ fc2w,
                        bf16* __restrict__ wqkv, bf16* __restrict__ wproj,
                        bf16* __restrict__ w1, bf16* __restrict__ w2)
{
    int i = blockIdx.x * 256 + threadIdx.x;
    if (i < 49152)        wqkv [i]          = __float2bfloat16_rn(qkvw [i]);
    else if (i < 65536)   wproj[i - 49152]  = __float2bfloat16_rn(projw[i - 49152]);
    else if (i < 131072)  w1   [i - 65536]  = __float2bfloat16_rn(fc1w [i - 65536]);
    else if (i < 196608)  w2   [i - 131072] = __float2bfloat16_rn(fc2w [i - 131072]);
}

// ---------------------------------------------------------------------------
// QKV GEMM: C[M,384] = xsb @ wqkv^T + bias, bf16 out. K=128.
// ---------------------------------------------------------------------------
__global__ __launch_bounds__(256, 2)
void gemm_qkv(const bf16* __restrict__ A, const bf16* __restrict__ Bw,
              const float* __restrict__ bias, bf16* __restrict__ C)
{
    extern __shared__ char dsm[];
    const uint32_t sbase = (smem_u32(dsm) + 127u) & ~127u;
    const int tid = threadIdx.x, lane = tid & 31, w = tid >> 5;
    const int wm = w & 3, wn = w >> 2;
    const int m0 = blockIdx.y * 128, n0 = blockIdx.x * 128;

    float acc[2][8][4];
    #pragma unroll
    for (int i = 0; i < 2; i++) for (int j = 0; j < 8; j++) for (int q = 0; q < 4; q++)
        acc[i][j][q] = 0.0f;

    const int a_row = wm * 32 + ((lane >> 3) & 1) * 8 + (lane & 7);
    const int a_kof = (lane >> 4) * 8;
    const int b_row = wn * 64 + (lane >> 4) * 8 + (lane & 7);
    const int b_kof = ((lane >> 3) & 1) * 8;

    load_chunk<128>(sbase, A, Bw, m0, n0, 0, tid);
    load_chunk<128>(sbase + 32768u, A, Bw, m0, n0, 1, tid);
    asm volatile("cp.async.wait_group 1;" ::: "memory");
    __syncthreads();
    mma_chunk(sbase, sbase + 16384u, acc, a_row, a_kof, b_row, b_kof);
    asm volatile("cp.async.wait_group 0;" ::: "memory");
    __syncthreads();
    mma_chunk(sbase + 32768u, sbase + 49152u, acc, a_row, a_kof, b_row, b_kof);

    const int er = lane >> 2, ec = (lane & 3) * 2;
    #pragma unroll
    for (int mi = 0; mi < 2; mi++) {
        #pragma unroll
        for (int ns = 0; ns < 8; ns++) {
            int row = m0 + wm * 32 + mi * 16 + er;
            int col = n0 + wn * 64 + ns * 8 + ec;
            float2 bb = *(const float2*)&bias[col];
            *(__nv_bfloat162*)&C[(size_t)row * 384 + col] =
                __floats2bfloat162_rn(acc[mi][ns][0] + bb.x, acc[mi][ns][1] + bb.y);
            *(__nv_bfloat162*)&C[(size_t)(row + 8) * 384 + col] =
                __floats2bfloat162_rn(acc[mi][ns][2] + bb.x, acc[mi][ns][3] + bb.y);
        }
    }
}

// ---------------------------------------------------------------------------
// Proj GEMM + residual + fused LN2: writes x2 (fp32) and xsb=LN2(x2) (bf16).
// Tile covers all 128 channels -> full rows per CTA; smem-atomic row reduce.
// ---------------------------------------------------------------------------
__global__ __launch_bounds__(256, 2)
void proj_ln(const bf16* __restrict__ A, const bf16* __restrict__ Bw,
             const float* __restrict__ bias, const float* __restrict__ res,
             const float* __restrict__ n2w, const float* __restrict__ n2b,
             float* __restrict__ x2, bf16* __restrict__ xsb)
{
    extern __shared__ char dsm[];
    __shared__ float rs[128], rq[128], smu[128], sst[128];
    const uint32_t sbase = (smem_u32(dsm) + 127u) & ~127u;
    const int tid = threadIdx.x, lane = tid & 31, w = tid >> 5;
    const int wm = w & 3, wn = w >> 2;
    const int m0 = blockIdx.x * 128;

    if (tid < 128) { rs[tid] = 0.0f; rq[tid] = 0.0f; }

    float acc[2][8][4];
    #pragma unroll
    for (int i = 0; i < 2; i++) for (int j = 0; j < 8; j++) for (int q = 0; q < 4; q++)
        acc[i][j][q] = 0.0f;

    const int a_row = wm * 32 + ((lane >> 3) & 1) * 8 + (lane & 7);
    const int a_kof = (lane >> 4) * 8;
    const int b_row = wn * 64 + (lane >> 4) * 8 + (lane & 7);
    const int b_kof = ((lane >> 3) & 1) * 8;

    load_chunk<128>(sbase, A, Bw, m0, 0, 0, tid);
    load_chunk<128>(sbase + 32768u, A, Bw, m0, 0, 1, tid);
    asm volatile("cp.async.wait_group 1;" ::: "memory");
    __syncthreads();
    mma_chunk(sbase, sbase + 16384u, acc, a_row, a_kof, b_row, b_kof);
    asm volatile("cp.async.wait_group 0;" ::: "memory");
    __syncthreads();
    mma_chunk(sbase + 32768u, sbase + 49152u, acc, a_row, a_kof, b_row, b_kof);

    // phase 1: v = acc + bias + res -> write x2, accumulate row sums
    const int er = lane >> 2, ec = (lane & 3) * 2;
    float ps0[2] = {0, 0}, ps1[2] = {0, 0}, pq0[2] = {0, 0}, pq1[2] = {0, 0};
    #pragma unroll
    for (int mi = 0; mi < 2; mi++) {
        #pragma unroll
        for (int ns = 0; ns < 8; ns++) {
            int lr  = wm * 32 + mi * 16 + er;
            int col = wn * 64 + ns * 8 + ec;
            int row = m0 + lr;
            float2 bb = *(const float2*)&bias[col];
            float2 r0 = *(const float2*)&res[(size_t)row * 128 + col];
            float2 r1 = *(const float2*)&res[(size_t)(row + 8) * 128 + col];
            float v0 = acc[mi][ns][0] + bb.x + r0.x;
            float v1 = acc[mi][ns][1] + bb.y + r0.y;
            float v2 = acc[mi][ns][2] + bb.x + r1.x;
            float v3 = acc[mi][ns][3] + bb.y + r1.y;
            acc[mi][ns][0] = v0; acc[mi][ns][1] = v1;
            acc[mi][ns][2] = v2; acc[mi][ns][3] = v3;
            *(float2*)&x2[(size_t)row * 128 + col]       = make_float2(v0, v1);
            *(float2*)&x2[(size_t)(row + 8) * 128 + col] = make_float2(v2, v3);
            ps0[mi] += v0 + v1;          pq0[mi] += v0*v0 + v1*v1;
            ps1[mi] += v2 + v3;          pq1[mi] += v2*v2 + v3*v3;
        }
    }
    #pragma unroll
    for (int mi = 0; mi < 2; mi++) {
        int lr = wm * 32 + mi * 16 + er;
        atomicAdd(&rs[lr], ps0[mi]);      atomicAdd(&rq[lr], pq0[mi]);
        atomicAdd(&rs[lr + 8], ps1[mi]);  atomicAdd(&rq[lr + 8], pq1[mi]);
    }
    __syncthreads();
    if (tid < 128) {
        float mu  = rs[tid] * (1.0f / 128.0f);
        float var = rq[tid] * (1.0f / 128.0f) - mu * mu;
        smu[tid] = mu;
        sst[tid] = rsqrtf(var + 1e-5f);
    }
    __syncthreads();

    // phase 2: xsb = LN(v)
    #pragma unroll
    for (int mi = 0; mi < 2; mi++) {
        #pragma unroll
        for (int ns = 0; ns < 8; ns++) {
            int lr  = wm * 32 + mi * 16 + er;
            int col = wn * 64 + ns * 8 + ec;
            int row = m0 + lr;
            float2 wv = *(const float2*)&n2w[col];
            float2 bv = *(const float2*)&n2b[col];
            float mu0 = smu[lr],     st0 = sst[lr];
            float mu1 = smu[lr + 8], st1 = sst[lr + 8];
            *(__nv_bfloat162*)&xsb[(size_t)row * 128 + col] =
                __floats2bfloat162_rn((acc[mi][ns][0] - mu0) * st0 * wv.x + bv.x,
                                      (acc[mi][ns][1] - mu0) * st0 * wv.y + bv.y);
            *(__nv_bfloat162*)&xsb[(size_t)(row + 8) * 128 + col] =
                __floats2bfloat162_rn((acc[mi][ns][2] - mu1) * st1 * wv.x + bv.x,
                                      (acc[mi][ns][3] - mu1) * st1 * wv.y + bv.y);
        }
    }
}

// ---------------------------------------------------------------------------
// Fused MLP: out = x2 + fc2( gelu( fc1(xsb) ) ), h never hits DRAM.
// A tile resident; 4 chunks of 128 h-cols; double-buffered weight streaming.
// ---------------------------------------------------------------------------
__global__ __launch_bounds__(256, 1)
void mlp_kernel(const bf16* __restrict__ Axs,
                const bf16* __restrict__ w1, const float* __restrict__ b1,
                const bf16* __restrict__ w2, const float* __restrict__ b2,
                const float* __restrict__ x2, float* __restrict__ out)
{
    extern __shared__ char dsm[];
    const uint32_t sbase = (smem_u32(dsm) + 127u) & ~127u;
    const uint32_t As = sbase, Hs = sbase + 32768u, B0 = sbase + 65536u, B1 = sbase + 98304u;
    const int tid = threadIdx.x, lane = tid & 31, w = tid >> 5;
    const int wm = w & 3, wn = w >> 2;
    const int m0 = blockIdx.x * 128;

    const int a_row = wm * 32 + ((lane >> 3) & 1) * 8 + (lane & 7);
    const int a_kof = (lane >> 4) * 8;
    const int b_row = wn * 64 + (lane >> 4) * 8 + (lane & 7);
    const int b_kof = ((lane >> 3) & 1) * 8;
    const int er = lane >> 2, ec = (lane & 3) * 2;

    float oacc[2][8][4];
    #pragma unroll
    for (int i = 0; i < 2; i++) for (int j = 0; j < 8; j++) for (int q = 0; q < 4; q++)
        oacc[i][j][q] = 0.0f;

    load_tile(As, Axs + (size_t)m0 * 128, 128, tid);
    load_tile(B0, w1, 128, tid);
    asm volatile("cp.async.commit_group;" ::: "memory");     // G: {A, w1_0}
    load_tile(B1, w2, 512, tid);
    asm volatile("cp.async.commit_group;" ::: "memory");     // G: {w2_0}

    #pragma unroll 1
    for (int j = 0; j < 4; j++) {
        asm volatile("cp.async.wait_group 1;" ::: "memory");  // w1_j (and A) ready
        __syncthreads();

        float hacc[2][8][4];
        #pragma unroll
        for (int i = 0; i < 2; i++) for (int jj = 0; jj < 8; jj++) for (int q = 0; q < 4; q++)
            hacc[i][jj][q] = 0.0f;
        #pragma unroll
        for (int c = 0; c < 2; c++)
            mma_chunk(As + c * 16384u, B0 + c * 16384u, hacc, a_row, a_kof, b_row, b_kof);

        // gelu + pack H -> Hs (bf16, swizzled 2-chunk layout)
        #pragma unroll
        for (int mi = 0; mi < 2; mi++) {
            #pragma unroll
            for (int ns = 0; ns < 8; ns++) {
                int lr  = wm * 32 + mi * 16 + er;
                int col = wn * 64 + ns * 8 + ec;
                float2 bb = *(const float2*)&b1[j * 128 + col];
                float v0 = hacc[mi][ns][0] + bb.x;
                float v1 = hacc[mi][ns][1] + bb.y;
                float v2 = hacc[mi][ns][2] + bb.x;
                float v3 = hacc[mi][ns][3] + bb.y;
                const float cst = 0.70710678118654752f;
                v0 = 0.5f * v0 * (1.0f + erff(v0 * cst));
                v1 = 0.5f * v1 * (1.0f + erff(v1 * cst));
                v2 = 0.5f * v2 * (1.0f + erff(v2 * cst));
                v3 = 0.5f * v3 * (1.0f + erff(v3 * cst));
                uint32_t ch = (uint32_t)(col >> 6) * 16384u;
                int cc = col & 63;
                uint32_t bo0 = (uint32_t)(lr * 128 + cc * 2);
                uint32_t bo1 = (uint32_t)((lr + 8) * 128 + cc * 2);
                *(__nv_bfloat162*)(dsm + (Hs - sbase) + ((sbase - smem_u32(dsm)))) ;
                // (addressing via raw smem stores below)
                uint32_t ad0 = Hs + ch + (bo0 ^ ((bo0 >> 3) & 0x70));
                uint32_t ad1 = Hs + ch + (bo1 ^ ((bo1 >> 3) & 0x70));
                __nv_bfloat162 p0 = __floats2bfloat162_rn(v0, v1);
                __nv_bfloat162 p1 = __floats2bfloat162_rn(v2, v3);
                asm volatile("st.shared.b32 [%0], %1;" :: "r"(ad0), "r"(*(uint32_t*)&p0));
                asm volatile("st.shared.b32 [%0], %1;" :: "r"(ad1), "r"(*(uint32_t*)&p1));
            }
        }
        __syncthreads();                                      // B0 reads + Hs writes done
        if (j < 3) {
            load_tile(B0, w1 + (size_t)(j + 1) * 128 * 128, 128, tid);
            asm volatile("cp.async.commit_group;" ::: "memory");
        }
        if (j < 3) { asm volatile("cp.async.wait_group 1;" ::: "memory"); }
        else       { asm volatile("cp.async.wait_group 0;" ::: "memory"); }
        __syncthreads();                                      // w2_j visible to all

        #pragma unroll
        for (int c = 0; c < 2; c++)
            mma_chunk(Hs + c * 16384u, B1 + c * 16384u, oacc, a_row, a_kof, b_row, b_kof);
        __syncthreads();                                      // B1 reads done
        if (j < 3) {
            load_tile(B1, w2 + (size_t)(j + 1) * 128, 512, tid);
            asm volatile("cp.async.commit_group;" ::: "memory");
        }
    }

    // epilogue: out = oacc + b2 + x2
    #pragma unroll
    for (int mi = 0; mi < 2; mi++) {
        #pragma unroll
        for (int ns = 0; ns < 8; ns++) {
            int lr  = wm * 32 + mi * 16 + er;
            int col = wn * 64 + ns * 8 + ec;
            int row = m0 + lr;
            float2 bb = *(const float2*)&b2[col];
            float2 r0 = *(const float2*)&x2[(size_t)row * 128 + col];
            float2 r1 = *(const float2*)&x2[(size_t)(row + 8) * 128 + col];
            *(float2*)&out[(size_t)row * 128 + col] =
                make_float2(oacc[mi][ns][0] + bb.x + r0.x, oacc[mi][ns][1] + bb.y + r0.y);
            *(float2*)&out[(size_t)(row + 8) * 128 + col] =
                make_float2(oacc[mi][ns][2] + bb.x + r1.x, oacc[mi][ns][3] + bb.y + r1.y);
        }
    }
}

// ---------------------------------------------------------------------------
// Sliding-window attention: warp per (token, head); bf16 in/out, fp32 math.
// ---------------------------------------------------------------------------
__global__ __launch_bounds__(256)
void attn_kernel(const bf16* __restrict__ qkv, const float* __restrict__ rpb,
                 bf16* __restrict__ out)
{
    int gw   = blockIdx.x * 8 + (threadIdx.x >> 5);
    int lane = threadIdx.x & 31;
    int h = gw & (NHEADS - 1);
    int t = gw >> 2;
    int n = t & (N_SEQ - 1);
    int bbase = t - n;

    int s = n - KS / 2;
    if (s < 0) s = 0;
    if (s > N_SEQ - KS) s = N_SEQ - KS;

    float q = __bfloat162float(qkv[(size_t)t * 384 + h * DHEAD + lane]) * 0.17677669529663687f;

    float logits[KS];
    #pragma unroll
    for (int j = 0; j < KS; j++) {
        float kx = __bfloat162float(qkv[(size_t)(bbase + s + j) * 384 + 128 + h * DHEAD + lane]);
        float p = q * kx;
        #pragma unroll
        for (int o = 16; o; o >>= 1) p += __shfl_xor_sync(0xffffffffu, p, o);
        logits[j] = p + rpb[h * (2 * KS - 1) + (s + j - n + KS - 1)];
    }

    float mx = logits[0];
    #pragma unroll
    for (int j = 1; j < KS; j++) mx = fmaxf(mx, logits[j]);

    float pj[KS], den = 0.0f;
    #pragma unroll
    for (int j = 0; j < KS; j++) { pj[j] = __expf(logits[j] - mx); den += pj[j]; }
    float inv = 1.0f / den;

    float o = 0.0f;
    #pragma unroll
    for (int j = 0; j < KS; j++) {
        float vx = __bfloat162float(qkv[(size_t)(bbase + s + j) * 384 + 256 + h * DHEAD + lane]);
        o += pj[j] * vx;
    }
    out[(size_t)t * 128 + h * DHEAD + lane] = __float2bfloat16_rn(o * inv);
}

// ---------------------------------------------------------------------------
extern "C" void kernel_launch(void* const* d_in, const int* in_sizes, int n_in,
                              void* d_out, int out_size)
{
    const float* x      = (const float*)d_in[0];
    const float* n1w    = (const float*)d_in[1];
    const float* n1b    = (const float*)d_in[2];
    const float* qkvw   = (const float*)d_in[3];
    const float* qkvb   = (const float*)d_in[4];
    const float* rpb    = (const float*)d_in[5];
    const float* projw  = (const float*)d_in[6];
    const float* projb  = (const float*)d_in[7];
    const float* n2w    = (const float*)d_in[8];
    const float* n2b    = (const float*)d_in[9];
    const float* fc1w   = (const float*)d_in[10];
    const float* fc1b   = (const float*)d_in[11];
    const float* fc2w   = (const float*)d_in[12];
    const float* fc2b   = (const float*)d_in[13];
    float* out = (float*)d_out;

    bf16 *xsb, *qkvb_s, *attnb, *wqkv, *wproj, *w1, *w2;
    float *x2;
    cudaGetSymbolAddress((void**)&xsb,    g_xsb);
    cudaGetSymbolAddress((void**)&qkvb_s, g_qkvb);
    cudaGetSymbolAddress((void**)&attnb,  g_attnb);
    cudaGetSymbolAddress((void**)&x2,     g_x2);
    cudaGetSymbolAddress((void**)&wqkv,   g_wqkv);
    cudaGetSymbolAddress((void**)&wproj,  g_wproj);
    cudaGetSymbolAddress((void**)&w1,     g_w1);
    cudaGetSymbolAddress((void**)&w2,     g_w2);

    const int SMEM_G = 65536 + 128;       // streaming GEMMs
    const int SMEM_M = 131072 + 128;      // fused MLP
    cudaFuncSetAttribute(gemm_qkv,   cudaFuncAttributeMaxDynamicSharedMemorySize, SMEM_G);
    cudaFuncSetAttribute(proj_ln,    cudaFuncAttributeMaxDynamicSharedMemorySize, SMEM_G);
    cudaFuncSetAttribute(mlp_kernel, cudaFuncAttributeMaxDynamicSharedMemorySize, SMEM_M);

    // 0. weights -> bf16 (one launch)
    cvt_all<<<768, 256>>>(qkvw, projw, fc1w, fc2w, wqkv, wproj, w1, w2);
    // 1. LN1 -> bf16
    ln_kernel<<<M_TOK / 8, 256>>>(x, n1w, n1b, xsb);
    // 2. QKV projection -> bf16
    gemm_qkv<<<dim3(3, M_TOK / 128), 256, SMEM_G>>>(xsb, wqkv, qkvb, qkvb_s);
    // 3. attention -> bf16
    attn_kernel<<<(M_TOK * NHEADS) / 8, 256>>>(qkvb_s, rpb, attnb);
    // 4. proj + residual + LN2 -> x2 (fp32) + xsb (bf16)
    proj_ln<<<M_TOK / 128, 256, SMEM_G>>>(attnb, wproj, projb, x, n2w, n2b, x2, xsb);
    // 5. fused MLP -> out
    mlp_kernel<<<M_TOK / 128, 256, SMEM_M>>>(xsb, w1, fc1b, w2, fc2b, x2, out);
}